// round 6
// baseline (speedup 1.0000x reference)
#include <cuda_runtime.h>
#include <math.h>
#include <stdint.h>

#define N_NODES 10000
#define N_EDGES 100000
#define FDIM 128

// ---------------- scratch (device globals; no allocations) ----------------
__device__ __align__(256) float g_sln[N_NODES * FDIM];
__device__ __align__(256) float g_Xln[N_NODES * 8 * FDIM];
__device__ __align__(256) float g_m1[N_NODES * 512];          // q | k | silu(gs1) | silu(gv1)
__device__ __align__(256) float g_x[N_NODES * FDIM];          // gs2 rows [0,128)
__device__ __align__(256) float g_v[N_NODES * 256];           // gv2 rows [128,384)
__device__ __align__(256) float g_edge[(size_t)N_EDGES * 640]; // t_attn | t_filter*cut | gt1o
__device__ __align__(256) float g_attn[N_EDGES * 8];
__device__ __align__(256) float g_amax[N_NODES * 8];
__device__ __align__(256) float g_den[N_NODES * 8];
__device__ __align__(256) int   g_deg[N_NODES];
__device__ __align__(256) int   g_off[N_NODES + 1];
__device__ __align__(256) int   g_cur[N_NODES];
__device__ __align__(256) int   g_elist[N_EDGES];
__device__ __align__(256) float g_w1n[N_NODES * 8 * FDIM];
__device__ __align__(256) float g_w2n[N_NODES * 8 * FDIM];
__device__ __align__(256) float g_wcatA[512 * 128];
__device__ __align__(256) float g_biasA[512];
__device__ __align__(256) float g_wcatE[640 * 128];
__device__ __align__(256) float g_biasE[640];

// ---------------- small helpers ----------------
__device__ __forceinline__ float bred(float v, int op, volatile float* sb) {
    #pragma unroll
    for (int o = 16; o; o >>= 1) {
        float u = __shfl_xor_sync(0xffffffffu, v, o);
        v = (op == 0) ? (v + u) : (op == 1) ? fmaxf(v, u) : fminf(v, u);
    }
    if ((threadIdx.x & 31) == 0) sb[threadIdx.x >> 5] = v;
    __syncthreads();
    float r = sb[0];
    #pragma unroll
    for (int i = 1; i < 4; i++)
        r = (op == 0) ? (r + sb[i]) : (op == 1) ? fmaxf(r, sb[i]) : fminf(r, sb[i]);
    __syncthreads();
    return r;
}

__device__ __forceinline__ float f2tf(float x) {
    uint32_t r;
    asm("cvt.rna.tf32.f32 %0, %1;" : "=r"(r) : "f"(x));
    return __uint_as_float(r);
}

// ---------------- CSR build ----------------
__global__ void zero_int_k() {
    int i = blockIdx.x * 256 + threadIdx.x;
    if (i < N_NODES) { g_deg[i] = 0; g_cur[i] = 0; }
}
__global__ void count_k(const int* __restrict__ ec) {
    int e = blockIdx.x * 256 + threadIdx.x;
    if (e < N_EDGES) {
        int c = ec[e];
        if (c >= 0 && c < N_NODES) atomicAdd(&g_deg[c], 1);
    }
}
__global__ void scan_k() {
    __shared__ int sh[1024];
    int t = threadIdx.x;
    if (t == 0) g_off[0] = 0;
    int carry = 0;
    for (int base = 0; base < N_NODES; base += 1024) {
        int i = base + t;
        int v = (i < N_NODES) ? g_deg[i] : 0;
        sh[t] = v;
        __syncthreads();
        for (int st = 1; st < 1024; st <<= 1) {
            int add = (t >= st) ? sh[t - st] : 0;
            __syncthreads();
            sh[t] += add;
            __syncthreads();
        }
        if (i < N_NODES) g_off[i + 1] = sh[t] + carry;
        carry += sh[1023];
        __syncthreads();
    }
}
__global__ void scatter_k(const int* __restrict__ ec) {
    int e = blockIdx.x * 256 + threadIdx.x;
    if (e < N_EDGES) {
        int c = ec[e];
        if (c >= 0 && c < N_NODES) {
            int p = atomicAdd(&g_cur[c], 1);
            g_elist[g_off[c] + p] = e;
        }
    }
}

// ---------------- node preprocessing: LayerNorm + maxmin-norm ----------------
__global__ void __launch_bounds__(128) node_prep_k(
    const float* __restrict__ s, const float* __restrict__ X,
    const float* __restrict__ lnw, const float* __restrict__ lnb,
    const float* __restrict__ tlnw)
{
    __shared__ float sb[4];
    int nd = blockIdx.x, f = threadIdx.x;
    float v = s[nd * FDIM + f];
    float mean = bred(v, 0, sb) * (1.0f / 128.0f);
    float e = v - mean;
    float var = bred(e * e, 0, sb) * (1.0f / 128.0f);
    g_sln[nd * FDIM + f] = e * rsqrtf(var + 1e-5f) * lnw[f] + lnb[f];

    float xv[8];
    #pragma unroll
    for (int l = 0; l < 8; l++) xv[l] = X[(size_t)nd * 1024 + l * 128 + f];
    float d3 = sqrtf(xv[0]*xv[0] + xv[1]*xv[1] + xv[2]*xv[2]);
    d3 = fmaxf(d3, 1e-12f);
    float s5 = 0.f;
    #pragma unroll
    for (int l = 3; l < 8; l++) s5 += xv[l]*xv[l];
    float d5 = fmaxf(sqrtf(s5), 1e-12f);

    float mx3 = bred(d3, 1, sb), mn3 = bred(d3, 2, sb);
    float mx5 = bred(d5, 1, sb), mn5 = bred(d5, 2, sb);
    float del3 = mx3 - mn3; if (del3 == 0.f) del3 = 1.f;
    float del5 = mx5 - mn5; if (del5 == 0.f) del5 = 1.f;
    float dn3 = fmaxf((d3 - mn3) / del3, 0.f);
    float dn5 = fmaxf((d5 - mn5) / del5, 0.f);
    float tw = tlnw[f];
    float c3 = dn3 / d3 * tw;
    float c5 = dn5 / d5 * tw;
    #pragma unroll
    for (int l = 0; l < 3; l++) g_Xln[(size_t)nd * 1024 + l * 128 + f] = xv[l] * c3;
    #pragma unroll
    for (int l = 3; l < 8; l++) g_Xln[(size_t)nd * 1024 + l * 128 + f] = xv[l] * c5;
}

// ---------------- weight concat ----------------
__global__ void concatA_k(const float* wq, const float* wk, const float* g1, const float* v1,
                          const float* bq, const float* bk, const float* b1, const float* bv)
{
    int i = blockIdx.x * 256 + threadIdx.x;
    if (i < 512 * 128) {
        int r = i >> 7;
        float w;
        if (r < 128) w = wq[i];
        else if (r < 256) w = wk[i - 128*128];
        else if (r < 384) w = g1[i - 256*128];
        else w = v1[i - 384*128];
        g_wcatA[i] = w;
    }
    if (i < 512) {
        float b;
        if (i < 128) b = bq[i];
        else if (i < 256) b = bk[i - 128];
        else if (i < 384) b = b1[i - 256];
        else b = bv[i - 384];
        g_biasA[i] = b;
    }
}
__global__ void concatE_k(const float* wre, const float* wrs, const float* wgt,
                          const float* bre, const float* brs, const float* bgt)
{
    int i = blockIdx.x * 256 + threadIdx.x;
    if (i < 640 * 128) {
        int r = i >> 7;
        float w;
        if (r < 128) w = wre[i];
        else if (r < 512) w = wrs[i - 128*128];
        else w = wgt[i - 512*128];
        g_wcatE[i] = w;
    }
    if (i < 640) {
        float b;
        if (i < 128) b = bre[i];
        else if (i < 512) b = brs[i - 128];
        else b = bgt[i - 512];
        g_biasE[i] = b;
    }
}

// ---------------- tf32 tensor-core GEMM, double-buffered + reg prefetch --------
// C[MxN] = A[Mx128] @ W[Nx128]^T (+bias, silu range, cutoff range).
// grid.z batching: A += z*za, C += z*zc, and W := Walt when z >= 3 (Wvk select).
__global__ void __launch_bounds__(256) gemm_tf32(
    const float* __restrict__ A, int lda,
    const float* __restrict__ W, const float* __restrict__ Walt,
    const float* __restrict__ bias,
    float* __restrict__ C, int ldc,
    int M,
    int silu_lo, int silu_hi,
    const float* __restrict__ dcut, int cut_lo, int cut_hi,
    int za, int zc)
{
    if (blockIdx.z) {
        A += (size_t)blockIdx.z * za;
        C += (size_t)blockIdx.z * zc;
        if (Walt && blockIdx.z >= 3) W = Walt;
    }
    __shared__ float As[2][16][132];
    __shared__ float Bs[2][16][132];
    const int t = threadIdx.x;
    const int wid = t >> 5, lane = t & 31;
    const int lr = lane >> 2;          // 0..7
    const int lc = lane & 3;           // 0..3
    const int wm = (wid & 3) * 32;     // warp row offset in tile
    const int wn = (wid >> 2) * 64;    // warp col offset in tile
    const int m0 = blockIdx.y * 128;
    const int n0 = blockIdx.x * 128;

    float acc[2][8][4];
    #pragma unroll
    for (int a = 0; a < 2; a++)
        #pragma unroll
        for (int b = 0; b < 8; b++)
            #pragma unroll
            for (int c = 0; c < 4; c++) acc[a][b][c] = 0.f;

    float4 ra[2], rb[2];
    float4 zero4 = make_float4(0.f, 0.f, 0.f, 0.f);

    // load panel 0 into registers
    #pragma unroll
    for (int i = 0; i < 2; i++) {
        int lin = t + i * 256;
        int ml = lin >> 2;
        int kk = (lin & 3) << 2;
        int m = m0 + ml;
        ra[i] = (m < M) ? *(const float4*)(A + (size_t)m * lda + kk) : zero4;
        rb[i] = *(const float4*)(W + (size_t)(n0 + ml) * 128 + kk);
    }

    #pragma unroll
    for (int p = 0; p < 8; p++) {
        const int buf = p & 1;
        // store current panel to smem (tf32-rounded)
        #pragma unroll
        for (int i = 0; i < 2; i++) {
            int lin = t + i * 256;
            int ml = lin >> 2;
            int kk = (lin & 3) << 2;
            As[buf][kk][ml]   = f2tf(ra[i].x);
            As[buf][kk+1][ml] = f2tf(ra[i].y);
            As[buf][kk+2][ml] = f2tf(ra[i].z);
            As[buf][kk+3][ml] = f2tf(ra[i].w);
            Bs[buf][kk][ml]   = f2tf(rb[i].x);
            Bs[buf][kk+1][ml] = f2tf(rb[i].y);
            Bs[buf][kk+2][ml] = f2tf(rb[i].z);
            Bs[buf][kk+3][ml] = f2tf(rb[i].w);
        }
        __syncthreads();
        // prefetch next panel while computing this one
        if (p < 7) {
            int k0n = (p + 1) * 16;
            #pragma unroll
            for (int i = 0; i < 2; i++) {
                int lin = t + i * 256;
                int ml = lin >> 2;
                int kk = (lin & 3) << 2;
                int m = m0 + ml;
                ra[i] = (m < M) ? *(const float4*)(A + (size_t)m * lda + k0n + kk) : zero4;
                rb[i] = *(const float4*)(W + (size_t)(n0 + ml) * 128 + k0n + kk);
            }
        }
        // compute: 2 ksteps of 8
        #pragma unroll
        for (int kk = 0; kk < 16; kk += 8) {
            uint32_t afr[2][4];
            #pragma unroll
            for (int mt = 0; mt < 2; mt++) {
                int mb = wm + mt * 16;
                afr[mt][0] = __float_as_uint(As[buf][kk + lc][mb + lr]);
                afr[mt][1] = __float_as_uint(As[buf][kk + lc][mb + lr + 8]);
                afr[mt][2] = __float_as_uint(As[buf][kk + 4 + lc][mb + lr]);
                afr[mt][3] = __float_as_uint(As[buf][kk + 4 + lc][mb + lr + 8]);
            }
            #pragma unroll
            for (int nt = 0; nt < 8; nt++) {
                int nb = wn + nt * 8;
                uint32_t b0 = __float_as_uint(Bs[buf][kk + lc][nb + lr]);
                uint32_t b1 = __float_as_uint(Bs[buf][kk + 4 + lc][nb + lr]);
                #pragma unroll
                for (int mt = 0; mt < 2; mt++) {
                    asm volatile(
                        "mma.sync.aligned.m16n8k8.row.col.f32.tf32.tf32.f32 "
                        "{%0,%1,%2,%3}, {%4,%5,%6,%7}, {%8,%9}, {%0,%1,%2,%3};"
                        : "+f"(acc[mt][nt][0]), "+f"(acc[mt][nt][1]),
                          "+f"(acc[mt][nt][2]), "+f"(acc[mt][nt][3])
                        : "r"(afr[mt][0]), "r"(afr[mt][1]), "r"(afr[mt][2]), "r"(afr[mt][3]),
                          "r"(b0), "r"(b1));
                }
            }
        }
    }

    // epilogue
    #pragma unroll
    for (int mt = 0; mt < 2; mt++) {
        int mr0 = m0 + wm + mt * 16 + lr;
        int mr1 = mr0 + 8;
        float cv0 = 1.f, cv1 = 1.f;
        if (dcut) {
            if (mr0 < M) {
                float d = dcut[mr0];
                cv0 = (d < 5.0f) ? 0.5f * (cosf(d * 0.62831853071795865f) + 1.f) : 0.f;
            }
            if (mr1 < M) {
                float d = dcut[mr1];
                cv1 = (d < 5.0f) ? 0.5f * (cosf(d * 0.62831853071795865f) + 1.f) : 0.f;
            }
        }
        #pragma unroll
        for (int nt = 0; nt < 8; nt++) {
            int n = n0 + wn + nt * 8 + 2 * lc;
            float v0 = acc[mt][nt][0], v1 = acc[mt][nt][1];
            float v2 = acc[mt][nt][2], v3 = acc[mt][nt][3];
            if (bias) {
                float b0 = bias[n], b1 = bias[n + 1];
                v0 += b0; v1 += b1; v2 += b0; v3 += b1;
            }
            if (n >= silu_lo && n < silu_hi) {
                v0 = v0 / (1.f + expf(-v0));
                v2 = v2 / (1.f + expf(-v2));
            }
            if (n + 1 >= silu_lo && n + 1 < silu_hi) {
                v1 = v1 / (1.f + expf(-v1));
                v3 = v3 / (1.f + expf(-v3));
            }
            if (dcut) {
                if (n >= cut_lo && n < cut_hi)         { v0 *= cv0; v2 *= cv1; }
                if (n + 1 >= cut_lo && n + 1 < cut_hi) { v1 *= cv0; v3 *= cv1; }
            }
            if (mr0 < M) {
                C[(size_t)mr0 * ldc + n]     = v0;
                C[(size_t)mr0 * ldc + n + 1] = v1;
            }
            if (mr1 < M) {
                C[(size_t)mr1 * ldc + n]     = v2;
                C[(size_t)mr1 * ldc + n + 1] = v3;
            }
        }
    }
}

// ---------------- attention scores ----------------
__global__ void attn_raw_k(const int* __restrict__ ec, const int* __restrict__ en) {
    int idx = blockIdx.x * 128 + threadIdx.x;
    if (idx >= N_EDGES * 8) return;
    int e = idx >> 3, h = idx & 7;
    const float4* q  = (const float4*)(g_m1 + (size_t)ec[e] * 512 + h * 16);
    const float4* kk = (const float4*)(g_m1 + (size_t)en[e] * 512 + 128 + h * 16);
    const float4* tt = (const float4*)(g_edge + (size_t)e * 640 + h * 16);
    float acc = 0.f;
    #pragma unroll
    for (int i = 0; i < 4; i++) {
        float4 a = q[i], b = kk[i], c = tt[i];
        acc += a.x*b.x*c.x + a.y*b.y*c.y + a.z*b.z*c.z + a.w*b.w*c.w;
    }
    g_attn[idx] = acc;
}

__global__ void stats_k() {
    int idx = blockIdx.x * 128 + threadIdx.x;
    if (idx >= N_NODES * 8) return;
    int n = idx >> 3, h = idx & 7;
    int b0 = g_off[n], b1 = g_off[n + 1];
    float m = -1e30f;
    for (int i = b0; i < b1; i++) m = fmaxf(m, g_attn[g_elist[i] * 8 + h]);
    float s = 0.f;
    for (int i = b0; i < b1; i++) s += expf(g_attn[g_elist[i] * 8 + h] - m);
    g_amax[idx] = m;
    g_den[idx]  = s;
}

__global__ void norm_k(const int* __restrict__ ec) {
    int idx = blockIdx.x * 128 + threadIdx.x;
    if (idx >= N_EDGES * 8) return;
    int e = idx >> 3, h = idx & 7;
    int c = ec[e];
    float a = expf(g_attn[idx] - g_amax[c * 8 + h]) / g_den[c * 8 + h];
    a *= sqrtf((float)g_deg[c]) * 0.088388347648318447f; // 1/sqrt(128)
    g_attn[idx] = a;
}

// ---------------- edge aggregation into s_out / X_out ----------------
__global__ void __launch_bounds__(128) aggregate_k(
    const int* __restrict__ en, const float* __restrict__ rl,
    float* __restrict__ sout, float* __restrict__ Xout)
{
    int nd = blockIdx.x, f = threadIdx.x;
    float sacc = g_sln[nd * FDIM + f];
    float xa[8];
    #pragma unroll
    for (int l = 0; l < 8; l++) xa[l] = g_Xln[(size_t)nd * 1024 + l * 128 + f];
    const int hs = f / 48, hd = (128 + f) / 48, ht = (256 + f) / 48;
    int b0 = g_off[nd], b1 = g_off[nd + 1];
    for (int i = b0; i < b1; i++) {
        int e = g_elist[i];
        int n = en[e];
        float a_s = g_attn[e * 8 + hs];
        float a_d = g_attn[e * 8 + hd];
        float a_t = g_attn[e * 8 + ht];
        const float* tf = g_edge + (size_t)e * 640 + 128;
        float os = g_x[n * FDIM + f]      * tf[f]       * a_s;
        float od = g_v[n * 256 + f]       * tf[128 + f] * a_d;
        float ot = g_v[n * 256 + 128 + f] * tf[256 + f] * a_t;
        sacc += os;
        const float* xlnN = g_Xln + (size_t)n * 1024 + f;
        const float* rle = rl + (size_t)e * 8;
        #pragma unroll
        for (int l = 0; l < 8; l++)
            xa[l] += od * __ldg(rle + l) + ot * xlnN[l * 128];
    }
    sout[nd * FDIM + f] = sacc;
    #pragma unroll
    for (int l = 0; l < 8; l++) Xout[(size_t)nd * 1024 + l * 128 + f] = xa[l];
}

// ---------------- final edge kernel: f_out ----------------
__global__ void __launch_bounds__(128) final_k(
    const float* __restrict__ fij, const float* __restrict__ rl,
    const int* __restrict__ ec, const int* __restrict__ en,
    float* __restrict__ fout)
{
    int e = blockIdx.x, f = threadIdx.x;
    int c = ec[e], n = en[e];
    float rr[8], w1v[8], w2v[8];
    #pragma unroll
    for (int l = 0; l < 8; l++) {
        rr[l]  = __ldg(rl + (size_t)e * 8 + l);
        w1v[l] = g_w1n[(size_t)c * 1024 + l * 128 + f];
        w2v[l] = g_w2n[(size_t)n * 1024 + l * 128 + f];
    }
    float d1 = 0.f, d2 = 0.f;
    #pragma unroll
    for (int l = 0; l < 8; l++) { d1 += w1v[l] * rr[l]; d2 += w2v[l] * rr[l]; }
    float wd = 0.f;
    #pragma unroll
    for (int l = 0; l < 8; l++)
        wd += (w1v[l] - d1 * rr[l]) * (w2v[l] - d2 * rr[l]);
    fout[(size_t)e * FDIM + f] = fij[(size_t)e * FDIM + f] + g_edge[(size_t)e * 640 + 512 + f] * wd;
}

// ---------------- launch ----------------
extern "C" void kernel_launch(void* const* d_in, const int* in_sizes, int n_in,
                              void* d_out, int out_size)
{
    (void)in_sizes; (void)out_size;
    if (n_in < 30) return;
    const float* s    = (const float*)d_in[0];
    const float* X    = (const float*)d_in[1];
    const float* fij  = (const float*)d_in[2];
    const float* rl   = (const float*)d_in[3];
    const float* dij  = (const float*)d_in[4];
    const int*   ec   = (const int*)d_in[5];
    const int*   en   = (const int*)d_in[6];
    const float* lnw  = (const float*)d_in[7];
    const float* lnb  = (const float*)d_in[8];
    const float* tlnw = (const float*)d_in[9];
    const float* wq   = (const float*)d_in[10];
    const float* bq   = (const float*)d_in[11];
    const float* wk   = (const float*)d_in[12];
    const float* bk   = (const float*)d_in[13];
    const float* gs1w = (const float*)d_in[14];
    const float* gs1b = (const float*)d_in[15];
    const float* gs2w = (const float*)d_in[16];
    const float* gs2b = (const float*)d_in[17];
    const float* gv1w = (const float*)d_in[18];
    const float* gv1b = (const float*)d_in[19];
    const float* gv2w = (const float*)d_in[20];
    const float* gv2b = (const float*)d_in[21];
    const float* wrew = (const float*)d_in[22];
    const float* wreb = (const float*)d_in[23];
    const float* wrsw = (const float*)d_in[24];
    const float* wrsb = (const float*)d_in[25];
    const float* gt1w = (const float*)d_in[26];
    const float* gt1b = (const float*)d_in[27];
    const float* wvq  = (const float*)d_in[28];
    const float* wvk  = (const float*)d_in[29];

    float* out  = (float*)d_out;
    float* sout = out;
    float* Xout = out + N_NODES * FDIM;
    float* fout = out + N_NODES * FDIM + N_NODES * 8 * FDIM;

    float *p_sln, *p_m1, *p_x, *p_v, *p_edge, *p_w1n, *p_w2n, *p_wcatA, *p_biasA, *p_wcatE, *p_biasE;
    cudaGetSymbolAddress((void**)&p_sln,   g_sln);
    cudaGetSymbolAddress((void**)&p_m1,    g_m1);
    cudaGetSymbolAddress((void**)&p_x,     g_x);
    cudaGetSymbolAddress((void**)&p_v,     g_v);
    cudaGetSymbolAddress((void**)&p_edge,  g_edge);
    cudaGetSymbolAddress((void**)&p_w1n,   g_w1n);
    cudaGetSymbolAddress((void**)&p_w2n,   g_w2n);
    cudaGetSymbolAddress((void**)&p_wcatA, g_wcatA);
    cudaGetSymbolAddress((void**)&p_biasA, g_biasA);
    cudaGetSymbolAddress((void**)&p_wcatE, g_wcatE);
    cudaGetSymbolAddress((void**)&p_biasE, g_biasE);

    // CSR build
    zero_int_k<<<(N_NODES + 255) / 256, 256>>>();
    count_k<<<(N_EDGES + 255) / 256, 256>>>(ec);
    scan_k<<<1, 1024>>>();
    scatter_k<<<(N_EDGES + 255) / 256, 256>>>(ec);

    // node preprocessing
    node_prep_k<<<N_NODES, 128>>>(s, X, lnw, lnb, tlnw);

    // weight concat
    concatA_k<<<(512 * 128 + 255) / 256, 256>>>(wq, wk, gs1w, gv1w, bq, bk, gs1b, gv1b);
    concatE_k<<<(640 * 128 + 255) / 256, 256>>>(wrew, wrsw, gt1w, wreb, wrsb, gt1b);

    // node GEMMs (tf32 tensor cores, pipelined)
    gemm_tf32<<<dim3(4, 79), 256>>>(p_sln, 128, p_wcatA, nullptr, p_biasA, p_m1, 512, N_NODES,
                                    256, 512, nullptr, 0, 0, 0, 0);
    gemm_tf32<<<dim3(1, 79), 256>>>(p_m1 + 256, 512, gs2w, nullptr, gs2b, p_x, 128, N_NODES,
                                    0, 0, nullptr, 0, 0, 0, 0);
    gemm_tf32<<<dim3(2, 79), 256>>>(p_m1 + 384, 512, gv2w + 128 * 128, nullptr, gv2b + 128,
                                    p_v, 256, N_NODES, 0, 0, nullptr, 0, 0, 0, 0);

    // edge GEMM (t_attn | t_filter*cut | gt1 out)
    gemm_tf32<<<dim3(5, 782), 256>>>(fij, 128, p_wcatE, nullptr, p_biasE, p_edge, 640, N_EDGES,
                                     0, 0, dij, 128, 512, 0, 0);

    // attention
    attn_raw_k<<<(N_EDGES * 8 + 127) / 128, 128>>>(ec, en);
    stats_k<<<(N_NODES * 8 + 127) / 128, 128>>>();
    norm_k<<<(N_EDGES * 8 + 127) / 128, 128>>>(ec);

    // aggregate into s_out / X_out
    aggregate_k<<<N_NODES, 128>>>(en, rl, sout, Xout);

    // vector projections on X_out
    gemm_tf32<<<dim3(1, 625), 256>>>(Xout, 128, wvq, nullptr, nullptr, p_w1n, 128, N_NODES * 8,
                                     0, 0, nullptr, 0, 0, 0, 0);
    // w2: 8 slices in a single batched launch (z selects l; z>=3 uses Wvk[1])
    gemm_tf32<<<dim3(1, 79, 8), 256>>>(Xout, 1024, wvk, wvk + 128 * 128, nullptr,
                                       p_w2n, 1024, N_NODES, 0, 0, nullptr, 0, 0,
                                       128, 128);

    // f_out
    final_k<<<N_EDGES, 128>>>(fij, rl, ec, en, fout);
}

// round 7
// speedup vs baseline: 1.1727x; 1.1727x over previous
#include <cuda_runtime.h>
#include <cuda_fp16.h>
#include <math.h>
#include <stdint.h>

#define N_NODES 10000
#define N_EDGES 100000
#define FDIM 128

// ---------------- scratch (device globals; no allocations) ----------------
__device__ __align__(256) float  g_sln[N_NODES * FDIM];
__device__ __align__(256) float  g_Xln[N_NODES * 8 * FDIM];
__device__ __align__(256) float  g_m1[N_NODES * 512];           // q | k | silu(gs1) | silu(gv1)
__device__ __align__(256) float  g_x[N_NODES * FDIM];           // gs2 rows [0,128)
__device__ __align__(256) float  g_v[N_NODES * 256];            // gv2 rows [128,384)
__device__ __align__(256) float  g_edgeA[(size_t)N_EDGES * 128]; // t_attn (fp32)
__device__ __align__(256) __half g_edgeH[(size_t)N_EDGES * 512]; // t_filter*cut (384) | gt1o (128)
__device__ __align__(256) float  g_attn[N_EDGES * 8];
__device__ __align__(256) float  g_amax[N_NODES * 8];
__device__ __align__(256) float  g_den[N_NODES * 8];
__device__ __align__(256) int    g_deg[N_NODES];
__device__ __align__(256) int    g_off[N_NODES + 1];
__device__ __align__(256) int    g_cur[N_NODES];
__device__ __align__(256) int    g_elist[N_EDGES];
__device__ __align__(256) __half g_w1n[N_NODES * 8 * FDIM];
__device__ __align__(256) __half g_w2n[N_NODES * 8 * FDIM];
__device__ __align__(256) float  g_wcatA[512 * 128];
__device__ __align__(256) float  g_biasA[512];
__device__ __align__(256) float  g_wcatE[640 * 128];
__device__ __align__(256) float  g_biasE[640];

// ---------------- small helpers ----------------
__device__ __forceinline__ float bred(float v, int op, volatile float* sb) {
    #pragma unroll
    for (int o = 16; o; o >>= 1) {
        float u = __shfl_xor_sync(0xffffffffu, v, o);
        v = (op == 0) ? (v + u) : (op == 1) ? fmaxf(v, u) : fminf(v, u);
    }
    if ((threadIdx.x & 31) == 0) sb[threadIdx.x >> 5] = v;
    __syncthreads();
    float r = sb[0];
    #pragma unroll
    for (int i = 1; i < 4; i++)
        r = (op == 0) ? (r + sb[i]) : (op == 1) ? fmaxf(r, sb[i]) : fminf(r, sb[i]);
    __syncthreads();
    return r;
}

__device__ __forceinline__ float f2tf(float x) {
    uint32_t r;
    asm("cvt.rna.tf32.f32 %0, %1;" : "=r"(r) : "f"(x));
    return __uint_as_float(r);
}

// ---------------- CSR build ----------------
__global__ void zero_int_k() {
    int i = blockIdx.x * 256 + threadIdx.x;
    if (i < N_NODES) { g_deg[i] = 0; g_cur[i] = 0; }
}
__global__ void count_k(const int* __restrict__ ec) {
    int e = blockIdx.x * 256 + threadIdx.x;
    if (e < N_EDGES) {
        int c = ec[e];
        if (c >= 0 && c < N_NODES) atomicAdd(&g_deg[c], 1);
    }
}
__global__ void scan_k() {
    __shared__ int sh[1024];
    int t = threadIdx.x;
    if (t == 0) g_off[0] = 0;
    int carry = 0;
    for (int base = 0; base < N_NODES; base += 1024) {
        int i = base + t;
        int v = (i < N_NODES) ? g_deg[i] : 0;
        sh[t] = v;
        __syncthreads();
        for (int st = 1; st < 1024; st <<= 1) {
            int add = (t >= st) ? sh[t - st] : 0;
            __syncthreads();
            sh[t] += add;
            __syncthreads();
        }
        if (i < N_NODES) g_off[i + 1] = sh[t] + carry;
        carry += sh[1023];
        __syncthreads();
    }
}
__global__ void scatter_k(const int* __restrict__ ec) {
    int e = blockIdx.x * 256 + threadIdx.x;
    if (e < N_EDGES) {
        int c = ec[e];
        if (c >= 0 && c < N_NODES) {
            int p = atomicAdd(&g_cur[c], 1);
            g_elist[g_off[c] + p] = e;
        }
    }
}

// ---------------- node preprocessing: LayerNorm + maxmin-norm ----------------
__global__ void __launch_bounds__(128) node_prep_k(
    const float* __restrict__ s, const float* __restrict__ X,
    const float* __restrict__ lnw, const float* __restrict__ lnb,
    const float* __restrict__ tlnw)
{
    __shared__ float sb[4];
    int nd = blockIdx.x, f = threadIdx.x;
    float v = s[nd * FDIM + f];
    float mean = bred(v, 0, sb) * (1.0f / 128.0f);
    float e = v - mean;
    float var = bred(e * e, 0, sb) * (1.0f / 128.0f);
    g_sln[nd * FDIM + f] = e * rsqrtf(var + 1e-5f) * lnw[f] + lnb[f];

    float xv[8];
    #pragma unroll
    for (int l = 0; l < 8; l++) xv[l] = X[(size_t)nd * 1024 + l * 128 + f];
    float d3 = sqrtf(xv[0]*xv[0] + xv[1]*xv[1] + xv[2]*xv[2]);
    d3 = fmaxf(d3, 1e-12f);
    float s5 = 0.f;
    #pragma unroll
    for (int l = 3; l < 8; l++) s5 += xv[l]*xv[l];
    float d5 = fmaxf(sqrtf(s5), 1e-12f);

    float mx3 = bred(d3, 1, sb), mn3 = bred(d3, 2, sb);
    float mx5 = bred(d5, 1, sb), mn5 = bred(d5, 2, sb);
    float del3 = mx3 - mn3; if (del3 == 0.f) del3 = 1.f;
    float del5 = mx5 - mn5; if (del5 == 0.f) del5 = 1.f;
    float dn3 = fmaxf((d3 - mn3) / del3, 0.f);
    float dn5 = fmaxf((d5 - mn5) / del5, 0.f);
    float tw = tlnw[f];
    float c3 = dn3 / d3 * tw;
    float c5 = dn5 / d5 * tw;
    #pragma unroll
    for (int l = 0; l < 3; l++) g_Xln[(size_t)nd * 1024 + l * 128 + f] = xv[l] * c3;
    #pragma unroll
    for (int l = 3; l < 8; l++) g_Xln[(size_t)nd * 1024 + l * 128 + f] = xv[l] * c5;
}

// ---------------- weight concat ----------------
__global__ void concatA_k(const float* wq, const float* wk, const float* g1, const float* v1,
                          const float* bq, const float* bk, const float* b1, const float* bv)
{
    int i = blockIdx.x * 256 + threadIdx.x;
    if (i < 512 * 128) {
        int r = i >> 7;
        float w;
        if (r < 128) w = wq[i];
        else if (r < 256) w = wk[i - 128*128];
        else if (r < 384) w = g1[i - 256*128];
        else w = v1[i - 384*128];
        g_wcatA[i] = w;
    }
    if (i < 512) {
        float b;
        if (i < 128) b = bq[i];
        else if (i < 256) b = bk[i - 128];
        else if (i < 384) b = b1[i - 256];
        else b = bv[i - 384];
        g_biasA[i] = b;
    }
}
__global__ void concatE_k(const float* wre, const float* wrs, const float* wgt,
                          const float* bre, const float* brs, const float* bgt)
{
    int i = blockIdx.x * 256 + threadIdx.x;
    if (i < 640 * 128) {
        int r = i >> 7;
        float w;
        if (r < 128) w = wre[i];
        else if (r < 512) w = wrs[i - 128*128];
        else w = wgt[i - 512*128];
        g_wcatE[i] = w;
    }
    if (i < 640) {
        float b;
        if (i < 128) b = bre[i];
        else if (i < 512) b = brs[i - 128];
        else b = bgt[i - 512];
        g_biasE[i] = b;
    }
}

// ---------------- tf32 tensor-core GEMM (round-4 inner loop) ------------------
// C[MxN] = A[Mx128] @ W[Nx128]^T (+bias, silu range, cutoff range).
// Columns >= half_lo are written as fp16 into Ch at column (n - half_lo).
// grid.z batching: A += z*za (floats), C += z*zcf, Ch += z*zch; W:=Walt when z>=3.
__global__ void __launch_bounds__(256) gemm_tf32(
    const float* __restrict__ A, int lda,
    const float* __restrict__ W, const float* __restrict__ Walt,
    const float* __restrict__ bias,
    float* __restrict__ C, int ldc,
    __half* __restrict__ Ch, int ldch, int half_lo,
    int M,
    int silu_lo, int silu_hi,
    const float* __restrict__ dcut, int cut_lo, int cut_hi,
    int za, int zcf, int zch)
{
    if (blockIdx.z) {
        A += (size_t)blockIdx.z * za;
        if (C)  C  += (size_t)blockIdx.z * zcf;
        if (Ch) Ch += (size_t)blockIdx.z * zch;
        if (Walt && blockIdx.z >= 3) W = Walt;
    }
    __shared__ float As[32][132];
    __shared__ float Bs[32][132];
    const int t = threadIdx.x;
    const int wid = t >> 5, lane = t & 31;
    const int lr = lane >> 2;          // 0..7
    const int lc = lane & 3;           // 0..3
    const int wm = (wid & 3) * 32;
    const int wn = (wid >> 2) * 64;
    const int m0 = blockIdx.y * 128;
    const int n0 = blockIdx.x * 128;

    float acc[2][8][4];
    #pragma unroll
    for (int a = 0; a < 2; a++)
        #pragma unroll
        for (int b = 0; b < 8; b++)
            #pragma unroll
            for (int c = 0; c < 4; c++) acc[a][b][c] = 0.f;

    for (int k0 = 0; k0 < 128; k0 += 32) {
        #pragma unroll
        for (int i = 0; i < 4; i++) {
            int lin = t + i * 256;
            int ml = lin >> 3;
            int kk = (lin & 7) << 2;
            int m = m0 + ml;
            float4 v = make_float4(0.f, 0.f, 0.f, 0.f);
            if (m < M) v = *(const float4*)(A + (size_t)m * lda + k0 + kk);
            As[kk][ml]   = f2tf(v.x);
            As[kk+1][ml] = f2tf(v.y);
            As[kk+2][ml] = f2tf(v.z);
            As[kk+3][ml] = f2tf(v.w);
        }
        #pragma unroll
        for (int i = 0; i < 4; i++) {
            int lin = t + i * 256;
            int nl = lin >> 3;
            int kk = (lin & 7) << 2;
            float4 v = *(const float4*)(W + (size_t)(n0 + nl) * 128 + k0 + kk);
            Bs[kk][nl]   = f2tf(v.x);
            Bs[kk+1][nl] = f2tf(v.y);
            Bs[kk+2][nl] = f2tf(v.z);
            Bs[kk+3][nl] = f2tf(v.w);
        }
        __syncthreads();
        #pragma unroll
        for (int kk = 0; kk < 32; kk += 8) {
            uint32_t afr[2][4];
            #pragma unroll
            for (int mt = 0; mt < 2; mt++) {
                int mb = wm + mt * 16;
                afr[mt][0] = __float_as_uint(As[kk + lc][mb + lr]);
                afr[mt][1] = __float_as_uint(As[kk + lc][mb + lr + 8]);
                afr[mt][2] = __float_as_uint(As[kk + 4 + lc][mb + lr]);
                afr[mt][3] = __float_as_uint(As[kk + 4 + lc][mb + lr + 8]);
            }
            #pragma unroll
            for (int nt = 0; nt < 8; nt++) {
                int nb = wn + nt * 8;
                uint32_t b0 = __float_as_uint(Bs[kk + lc][nb + lr]);
                uint32_t b1 = __float_as_uint(Bs[kk + 4 + lc][nb + lr]);
                #pragma unroll
                for (int mt = 0; mt < 2; mt++) {
                    asm volatile(
                        "mma.sync.aligned.m16n8k8.row.col.f32.tf32.tf32.f32 "
                        "{%0,%1,%2,%3}, {%4,%5,%6,%7}, {%8,%9}, {%0,%1,%2,%3};"
                        : "+f"(acc[mt][nt][0]), "+f"(acc[mt][nt][1]),
                          "+f"(acc[mt][nt][2]), "+f"(acc[mt][nt][3])
                        : "r"(afr[mt][0]), "r"(afr[mt][1]), "r"(afr[mt][2]), "r"(afr[mt][3]),
                          "r"(b0), "r"(b1));
                }
            }
        }
        __syncthreads();
    }

    // epilogue
    #pragma unroll
    for (int mt = 0; mt < 2; mt++) {
        int mr0 = m0 + wm + mt * 16 + lr;
        int mr1 = mr0 + 8;
        float cv0 = 1.f, cv1 = 1.f;
        if (dcut) {
            if (mr0 < M) {
                float d = dcut[mr0];
                cv0 = (d < 5.0f) ? 0.5f * (cosf(d * 0.62831853071795865f) + 1.f) : 0.f;
            }
            if (mr1 < M) {
                float d = dcut[mr1];
                cv1 = (d < 5.0f) ? 0.5f * (cosf(d * 0.62831853071795865f) + 1.f) : 0.f;
            }
        }
        #pragma unroll
        for (int nt = 0; nt < 8; nt++) {
            int n = n0 + wn + nt * 8 + 2 * lc;
            float v0 = acc[mt][nt][0], v1 = acc[mt][nt][1];
            float v2 = acc[mt][nt][2], v3 = acc[mt][nt][3];
            if (bias) {
                float b0 = bias[n], b1 = bias[n + 1];
                v0 += b0; v1 += b1; v2 += b0; v3 += b1;
            }
            if (n >= silu_lo && n < silu_hi) {
                v0 = v0 / (1.f + expf(-v0));
                v2 = v2 / (1.f + expf(-v2));
            }
            if (n + 1 >= silu_lo && n + 1 < silu_hi) {
                v1 = v1 / (1.f + expf(-v1));
                v3 = v3 / (1.f + expf(-v3));
            }
            if (dcut) {
                if (n >= cut_lo && n < cut_hi)         { v0 *= cv0; v2 *= cv1; }
                if (n + 1 >= cut_lo && n + 1 < cut_hi) { v1 *= cv0; v3 *= cv1; }
            }
            if (n >= half_lo) {
                int nh = n - half_lo;
                if (mr0 < M) *(__half2*)(Ch + (size_t)mr0 * ldch + nh) = __floats2half2_rn(v0, v1);
                if (mr1 < M) *(__half2*)(Ch + (size_t)mr1 * ldch + nh) = __floats2half2_rn(v2, v3);
            } else {
                if (mr0 < M) {
                    C[(size_t)mr0 * ldc + n]     = v0;
                    C[(size_t)mr0 * ldc + n + 1] = v1;
                }
                if (mr1 < M) {
                    C[(size_t)mr1 * ldc + n]     = v2;
                    C[(size_t)mr1 * ldc + n + 1] = v3;
                }
            }
        }
    }
}

// ---------------- attention scores ----------------
__global__ void attn_raw_k(const int* __restrict__ ec, const int* __restrict__ en) {
    int idx = blockIdx.x * 128 + threadIdx.x;
    if (idx >= N_EDGES * 8) return;
    int e = idx >> 3, h = idx & 7;
    const float4* q  = (const float4*)(g_m1 + (size_t)ec[e] * 512 + h * 16);
    const float4* kk = (const float4*)(g_m1 + (size_t)en[e] * 512 + 128 + h * 16);
    const float4* tt = (const float4*)(g_edgeA + (size_t)e * 128 + h * 16);
    float acc = 0.f;
    #pragma unroll
    for (int i = 0; i < 4; i++) {
        float4 a = q[i], b = kk[i], c = tt[i];
        acc += a.x*b.x*c.x + a.y*b.y*c.y + a.z*b.z*c.z + a.w*b.w*c.w;
    }
    g_attn[idx] = acc;
}

__global__ void stats_k() {
    int idx = blockIdx.x * 128 + threadIdx.x;
    if (idx >= N_NODES * 8) return;
    int n = idx >> 3, h = idx & 7;
    int b0 = g_off[n], b1 = g_off[n + 1];
    float m = -1e30f;
    for (int i = b0; i < b1; i++) m = fmaxf(m, g_attn[g_elist[i] * 8 + h]);
    float s = 0.f;
    for (int i = b0; i < b1; i++) s += expf(g_attn[g_elist[i] * 8 + h] - m);
    g_amax[idx] = m;
    g_den[idx]  = s;
}

__global__ void norm_k(const int* __restrict__ ec) {
    int idx = blockIdx.x * 128 + threadIdx.x;
    if (idx >= N_EDGES * 8) return;
    int e = idx >> 3, h = idx & 7;
    int c = ec[e];
    float a = expf(g_attn[idx] - g_amax[c * 8 + h]) / g_den[c * 8 + h];
    a *= sqrtf((float)g_deg[c]) * 0.088388347648318447f; // 1/sqrt(128)
    g_attn[idx] = a;
}

// ---------------- edge aggregation into s_out / X_out ----------------
__global__ void __launch_bounds__(128) aggregate_k(
    const int* __restrict__ en, const float* __restrict__ rl,
    float* __restrict__ sout, float* __restrict__ Xout)
{
    int nd = blockIdx.x, f = threadIdx.x;
    float sacc = g_sln[nd * FDIM + f];
    float xa[8];
    #pragma unroll
    for (int l = 0; l < 8; l++) xa[l] = g_Xln[(size_t)nd * 1024 + l * 128 + f];
    const int hs = f / 48, hd = (128 + f) / 48, ht = (256 + f) / 48;
    int b0 = g_off[nd], b1 = g_off[nd + 1];
    for (int i = b0; i < b1; i++) {
        int e = g_elist[i];
        int n = en[e];
        float a_s = g_attn[e * 8 + hs];
        float a_d = g_attn[e * 8 + hd];
        float a_t = g_attn[e * 8 + ht];
        const __half* tf = g_edgeH + (size_t)e * 512;
        float os = g_x[n * FDIM + f]      * __half2float(tf[f])       * a_s;
        float od = g_v[n * 256 + f]       * __half2float(tf[128 + f]) * a_d;
        float ot = g_v[n * 256 + 128 + f] * __half2float(tf[256 + f]) * a_t;
        sacc += os;
        const float* xlnN = g_Xln + (size_t)n * 1024 + f;
        const float* rle = rl + (size_t)e * 8;
        #pragma unroll
        for (int l = 0; l < 8; l++)
            xa[l] += od * __ldg(rle + l) + ot * xlnN[l * 128];
    }
    sout[nd * FDIM + f] = sacc;
    #pragma unroll
    for (int l = 0; l < 8; l++) Xout[(size_t)nd * 1024 + l * 128 + f] = xa[l];
}

// ---------------- final edge kernel: f_out ----------------
__global__ void __launch_bounds__(128) final_k(
    const float* __restrict__ fij, const float* __restrict__ rl,
    const int* __restrict__ ec, const int* __restrict__ en,
    float* __restrict__ fout)
{
    int e = blockIdx.x, f = threadIdx.x;
    int c = ec[e], n = en[e];
    float rr[8], w1v[8], w2v[8];
    #pragma unroll
    for (int l = 0; l < 8; l++) {
        rr[l]  = __ldg(rl + (size_t)e * 8 + l);
        w1v[l] = __half2float(g_w1n[(size_t)c * 1024 + l * 128 + f]);
        w2v[l] = __half2float(g_w2n[(size_t)n * 1024 + l * 128 + f]);
    }
    float d1 = 0.f, d2 = 0.f;
    #pragma unroll
    for (int l = 0; l < 8; l++) { d1 += w1v[l] * rr[l]; d2 += w2v[l] * rr[l]; }
    float wd = 0.f;
    #pragma unroll
    for (int l = 0; l < 8; l++)
        wd += (w1v[l] - d1 * rr[l]) * (w2v[l] - d2 * rr[l]);
    float gt = __half2float(g_edgeH[(size_t)e * 512 + 384 + f]);
    fout[(size_t)e * FDIM + f] = fij[(size_t)e * FDIM + f] + gt * wd;
}

// ---------------- launch ----------------
extern "C" void kernel_launch(void* const* d_in, const int* in_sizes, int n_in,
                              void* d_out, int out_size)
{
    (void)in_sizes; (void)out_size;
    if (n_in < 30) return;
    const float* s    = (const float*)d_in[0];
    const float* X    = (const float*)d_in[1];
    const float* fij  = (const float*)d_in[2];
    const float* rl   = (const float*)d_in[3];
    const float* dij  = (const float*)d_in[4];
    const int*   ec   = (const int*)d_in[5];
    const int*   en   = (const int*)d_in[6];
    const float* lnw  = (const float*)d_in[7];
    const float* lnb  = (const float*)d_in[8];
    const float* tlnw = (const float*)d_in[9];
    const float* wq   = (const float*)d_in[10];
    const float* bq   = (const float*)d_in[11];
    const float* wk   = (const float*)d_in[12];
    const float* bk   = (const float*)d_in[13];
    const float* gs1w = (const float*)d_in[14];
    const float* gs1b = (const float*)d_in[15];
    const float* gs2w = (const float*)d_in[16];
    const float* gs2b = (const float*)d_in[17];
    const float* gv1w = (const float*)d_in[18];
    const float* gv1b = (const float*)d_in[19];
    const float* gv2w = (const float*)d_in[20];
    const float* gv2b = (const float*)d_in[21];
    const float* wrew = (const float*)d_in[22];
    const float* wreb = (const float*)d_in[23];
    const float* wrsw = (const float*)d_in[24];
    const float* wrsb = (const float*)d_in[25];
    const float* gt1w = (const float*)d_in[26];
    const float* gt1b = (const float*)d_in[27];
    const float* wvq  = (const float*)d_in[28];
    const float* wvk  = (const float*)d_in[29];

    float* out  = (float*)d_out;
    float* sout = out;
    float* Xout = out + N_NODES * FDIM;
    float* fout = out + N_NODES * FDIM + N_NODES * 8 * FDIM;

    float  *p_sln, *p_m1, *p_x, *p_v, *p_edgeA, *p_wcatA, *p_biasA, *p_wcatE, *p_biasE;
    __half *p_edgeH, *p_w1n, *p_w2n;
    cudaGetSymbolAddress((void**)&p_sln,   g_sln);
    cudaGetSymbolAddress((void**)&p_m1,    g_m1);
    cudaGetSymbolAddress((void**)&p_x,     g_x);
    cudaGetSymbolAddress((void**)&p_v,     g_v);
    cudaGetSymbolAddress((void**)&p_edgeA, g_edgeA);
    cudaGetSymbolAddress((void**)&p_edgeH, g_edgeH);
    cudaGetSymbolAddress((void**)&p_w1n,   g_w1n);
    cudaGetSymbolAddress((void**)&p_w2n,   g_w2n);
    cudaGetSymbolAddress((void**)&p_wcatA, g_wcatA);
    cudaGetSymbolAddress((void**)&p_biasA, g_biasA);
    cudaGetSymbolAddress((void**)&p_wcatE, g_wcatE);
    cudaGetSymbolAddress((void**)&p_biasE, g_biasE);

    const int BIG = 1 << 30;

    // CSR build
    zero_int_k<<<(N_NODES + 255) / 256, 256>>>();
    count_k<<<(N_EDGES + 255) / 256, 256>>>(ec);
    scan_k<<<1, 1024>>>();
    scatter_k<<<(N_EDGES + 255) / 256, 256>>>(ec);

    // node preprocessing
    node_prep_k<<<N_NODES, 128>>>(s, X, lnw, lnb, tlnw);

    // weight concat
    concatA_k<<<(512 * 128 + 255) / 256, 256>>>(wq, wk, gs1w, gv1w, bq, bk, gs1b, gv1b);
    concatE_k<<<(640 * 128 + 255) / 256, 256>>>(wrew, wrsw, gt1w, wreb, wrsb, gt1b);

    // node GEMMs (tf32 tensor cores)
    gemm_tf32<<<dim3(4, 79), 256>>>(p_sln, 128, p_wcatA, nullptr, p_biasA,
                                    p_m1, 512, nullptr, 0, BIG, N_NODES,
                                    256, 512, nullptr, 0, 0, 0, 0, 0);
    gemm_tf32<<<dim3(1, 79), 256>>>(p_m1 + 256, 512, gs2w, nullptr, gs2b,
                                    p_x, 128, nullptr, 0, BIG, N_NODES,
                                    0, 0, nullptr, 0, 0, 0, 0, 0);
    gemm_tf32<<<dim3(2, 79), 256>>>(p_m1 + 384, 512, gv2w + 128 * 128, nullptr, gv2b + 128,
                                    p_v, 256, nullptr, 0, BIG, N_NODES,
                                    0, 0, nullptr, 0, 0, 0, 0, 0);

    // edge GEMM: cols [0,128) -> fp32 t_attn; cols [128,640) -> fp16 (filter*cut | gt1o)
    gemm_tf32<<<dim3(5, 782), 256>>>(fij, 128, p_wcatE, nullptr, p_biasE,
                                     p_edgeA, 128, p_edgeH, 512, 128, N_EDGES,
                                     0, 0, dij, 128, 512, 0, 0, 0);

    // attention
    attn_raw_k<<<(N_EDGES * 8 + 127) / 128, 128>>>(ec, en);
    stats_k<<<(N_NODES * 8 + 127) / 128, 128>>>();
    norm_k<<<(N_EDGES * 8 + 127) / 128, 128>>>(ec);

    // aggregate into s_out / X_out
    aggregate_k<<<N_NODES, 128>>>(en, rl, sout, Xout);

    // vector projections on X_out -> fp16 tables
    gemm_tf32<<<dim3(1, 625), 256>>>(Xout, 128, wvq, nullptr, nullptr,
                                     nullptr, 0, p_w1n, 128, 0, N_NODES * 8,
                                     0, 0, nullptr, 0, 0, 0, 0, 0);
    gemm_tf32<<<dim3(1, 79, 8), 256>>>(Xout, 1024, wvk, wvk + 128 * 128, nullptr,
                                       nullptr, 0, p_w2n, 1024, 0, N_NODES,
                                       0, 0, nullptr, 0, 0, 128, 0, 128);

    // f_out
    final_k<<<N_EDGES, 128>>>(fij, rl, ec, en, fout);
}